// round 11
// baseline (speedup 1.0000x reference)
#include <cuda_runtime.h>
#include <cuda_fp16.h>
#include <stdint.h>

// Problem constants
#define B     1024
#define S     2048
#define R1    20000
#define R2    40000

#define MAIN_THREADS 512
#define NPART 3                    // part0 = rates_1st; part1,2 = rates_2nd halves
#define RPP   20000                // rates (and real entries) per partition
#define EPT   40                   // entries per thread per partition (pad 20480)
#define PART_PAD (EPT * MAIN_THREADS)   // 20480
#define KPAD  2048u                // pad-entry key (harmless acc slot)
#define ACC_SLOTS 2050
#define CHUNK 8

// ---------------- static device scratch (no runtime allocation) ----------------
// g_counts starts zero (static zero-init); scan_kernel re-zeroes after reading.
__device__ int       g_counts[NPART][S];
__device__ int       g_cur[NPART][S];
// Key-grouped, transposed entry streams.
//   part0:  e = ra | k<<11 | rid<<23            (11 + 12 + 15 bits)
//   part1+: e = ra | rb<<11 | k<<22 | rid<<34   (11 + 11 + 12 + 15 bits)
__device__ uint64_t  g_et[NPART][PART_PAD];

__device__ __forceinline__ int transposeP(int pos) {
    return (pos % EPT) * MAIN_THREADS + pos / EPT;
}

// Predicated fire-and-forget shared atomics. NO memory clobber: every other
// access to the accumulator region is separated from these reds by
// __syncthreads() (a full compiler + HW barrier), so ordering is guaranteed
// without fencing — and ptxas remains free to hoist the entry-stream LDGs
// across these instructions (this was R10's mistake).
__device__ __forceinline__ void pred_red2(unsigned pred, unsigned addr,
                                          float v0, float v1) {
    asm volatile(
        "{\n\t"
        ".reg .pred p;\n\t"
        "setp.ne.u32 p, %0, 0;\n\t"
        "@p red.shared.add.f32 [%1], %2;\n\t"
        "@p red.shared.add.f32 [%3], %4;\n\t"
        "}"
        :: "r"(pred), "r"(addr), "f"(v0), "r"(addr + 4), "f"(v1));
}

// ---------------- prep kernels ----------------

__global__ void hist_kernel(const int* __restrict__ inds_1p,
                            const int* __restrict__ inds_2p) {
    int i = blockIdx.x * blockDim.x + threadIdx.x;
    if (i < R1) {
        atomicAdd(&g_counts[0][inds_1p[i]], 1);
    } else if (i < R1 + R2) {
        int j = i - R1;
        atomicAdd(&g_counts[1 + (j >= RPP)][inds_2p[j]], 1);
    }
}

// One CTA per partition: exclusive scan over its 2048 bins -> running cursors.
// Re-zeroes its counts slice (restores the zero-at-entry invariant).
__global__ void scan_kernel() {
    __shared__ int buf[2][S];
    const int tid  = threadIdx.x;       // 1024 threads, 2 elems each
    const int part = blockIdx.x;

    int* cnt = g_counts[part];
    int* cur = g_cur[part];

    buf[0][tid]        = cnt[tid];
    buf[0][tid + 1024] = cnt[tid + 1024];
    cnt[tid]        = 0;
    cnt[tid + 1024] = 0;
    __syncthreads();

    int src = 0;
    for (int off = 1; off < S; off <<= 1) {
        int i0 = tid, i1 = tid + 1024;
        int v0 = buf[src][i0] + (i0 >= off ? buf[src][i0 - off] : 0);
        int v1 = buf[src][i1] + (i1 >= off ? buf[src][i1 - off] : 0);
        __syncthreads();
        buf[1 - src][i0] = v0;
        buf[1 - src][i1] = v1;
        __syncthreads();
        src ^= 1;
    }
    cur[tid]        = (tid == 0) ? 0 : buf[src][tid - 1];
    cur[tid + 1024] = buf[src][tid + 1023];
}

// Scatter entries into key-grouped transposed slots + write pad entries.
__global__ void scatter_pad_kernel(const int* __restrict__ inds_1r,
                                   const int* __restrict__ inds_1p,
                                   const int* __restrict__ inds_2r,
                                   const int* __restrict__ inds_2p) {
    int i = blockIdx.x * blockDim.x + threadIdx.x;
    if (i < R1) {
        int p   = inds_1p[i];
        int pos = atomicAdd(&g_cur[0][p], 1);
        g_et[0][transposeP(pos)] =
              (uint64_t)(uint32_t)inds_1r[i]
            | ((uint64_t)(uint32_t)p << 11)
            | ((uint64_t)(uint32_t)i << 23);
    } else if (i < R1 + R2) {
        int j    = i - R1;
        int part = 1 + (j >= RPP);
        int rrel = j - (part - 1) * RPP;
        int p    = inds_2p[j];
        int pos  = atomicAdd(&g_cur[part][p], 1);
        g_et[part][transposeP(pos)] =
              (uint64_t)(uint32_t)inds_2r[2 * j]
            | ((uint64_t)(uint32_t)inds_2r[2 * j + 1] << 11)
            | ((uint64_t)(uint32_t)p                  << 22)
            | ((uint64_t)(uint32_t)rrel               << 34);
    } else if (i < R1 + R2 + NPART * (PART_PAD - RPP)) {
        int q    = i - (R1 + R2);
        int part = q / (PART_PAD - RPP);
        int slot = RPP + q % (PART_PAD - RPP);
        uint64_t e = (part == 0) ? ((uint64_t)KPAD << 11) : ((uint64_t)KPAD << 22);
        g_et[part][transposeP(slot)] = e;
    }
}

// ---------------- main kernel ----------------
// TWO batch rows per CTA; random-read tables (y, rates) packed __half2
// {row0,row1}; fp32 register run accumulation. Run closes are predicated
// fire-and-forget red.shared.add (~1 in 10 entries active) with no fence,
// so there is no smem RMW dependency chain and entry-load batching (MLP=8)
// is preserved. Atomic closes are correct even for slice-boundary keys, so
// no boundary bookkeeping exists at all.
//
// SMEM: y2h(8KB) + acc2(16.4KB) + rbuf2h(80KB) = 104.6KB -> 2 CTAs/SM.

#define SMEM_BYTES (S * 4 + 2 * ACC_SLOTS * 4 + RPP * 4)

template <bool SECOND>
__device__ __forceinline__ void sweep2(
    const uint64_t* __restrict__ ep,      // g_et[part] + tid
    const __half2* __restrict__ y2h,
    const __half2* __restrict__ rbuf2h,
    unsigned acc_base)                     // smem u32 address of acc2[0]
{
    uint64_t buf0[CHUNK], buf1[CHUNK];
    #pragma unroll
    for (int u = 0; u < CHUNK; ++u)
        buf0[u] = ep[u * MAIN_THREADS];

    unsigned curk = 0;
    float a0 = 0.f, a1 = 0.f;

    #pragma unroll
    for (int c = 0; c < EPT / CHUNK; ++c) {
        uint64_t* cur = (c & 1) ? buf1 : buf0;
        uint64_t* nxt = (c & 1) ? buf0 : buf1;
        if (c + 1 < EPT / CHUNK) {
            const uint64_t* np = ep + (c + 1) * CHUNK * MAIN_THREADS;
            #pragma unroll
            for (int u = 0; u < CHUNK; ++u)
                nxt[u] = np[u * MAIN_THREADS];
        }
        #pragma unroll
        for (int u = 0; u < CHUNK; ++u) {
            uint64_t e = cur[u];
            unsigned k;
            float v0, v1;
            if (SECOND) {
                unsigned ra  = (unsigned)e & 2047u;
                unsigned rb  = ((unsigned)(e >> 11)) & 2047u;
                k            = ((unsigned)(e >> 22)) & 4095u;
                unsigned rid = (unsigned)(e >> 34);
                float2 fa = __half22float2(y2h[ra]);     // 1 random LDS.32
                float2 fb = __half22float2(y2h[rb]);     // 1 random LDS.32
                float2 fr = __half22float2(rbuf2h[rid]); // 1 random LDS.32
                v0 = fa.x * fb.x * fr.x;
                v1 = fa.y * fb.y * fr.y;
            } else {
                unsigned ra  = (unsigned)e & 2047u;
                k            = ((unsigned)(e >> 11)) & 4095u;
                unsigned rid = (unsigned)(e >> 23);
                float2 fa = __half22float2(y2h[ra]);
                float2 fr = __half22float2(rbuf2h[rid]);
                v0 = fa.x * fr.x;
                v1 = fa.y * fr.y;
            }
            if (c == 0 && u == 0) {
                curk = k; a0 = v0; a1 = v1;      // prime first run
            } else {
                unsigned diff = (k != curk) ? 1u : 0u;
                pred_red2(diff, acc_base + 8u * curk, a0, a1);  // close run (rare)
                a0 = diff ? v0 : (a0 + v0);
                a1 = diff ? v1 : (a1 + v1);
                curk = k;
            }
        }
    }
    pred_red2(1u, acc_base + 8u * curk, a0, a1);   // flush last run
}

__global__ __launch_bounds__(MAIN_THREADS, 2)
void reaction_main_kernel(const float* __restrict__ y_in,
                          const float* __restrict__ rates_1st,
                          const float* __restrict__ rates_2nd,
                          float* __restrict__ y_out) {
    extern __shared__ char smraw[];
    __half2* y2h    = (__half2*)smraw;                       // [S]
    float*   acc2   = (float*)(smraw + S * 4);               // [2*ACC_SLOTS]
    __half2* rbuf2h = (__half2*)(smraw + S * 4 + 2 * ACC_SLOTS * 4); // [RPP]

    const unsigned acc_base = (unsigned)__cvta_generic_to_shared(acc2);

    const int b0  = 2 * blockIdx.x;
    const int b1  = b0 + 1;
    const int tid = threadIdx.x;

    // Load two y rows -> packed half2 (vector STS); zero the accumulator.
    {
        const float4* s0 = (const float4*)(y_in + (size_t)b0 * S);
        const float4* s1 = (const float4*)(y_in + (size_t)b1 * S);
        float4 r0 = s0[tid], r1 = s1[tid];
        __half2 t[4];
        t[0] = __floats2half2_rn(r0.x, r1.x);
        t[1] = __floats2half2_rn(r0.y, r1.y);
        t[2] = __floats2half2_rn(r0.z, r1.z);
        t[3] = __floats2half2_rn(r0.w, r1.w);
        *(uint4*)(y2h + 4 * tid) = *(const uint4*)t;         // STS.128
        #pragma unroll
        for (int i = tid; i < 2 * ACC_SLOTS; i += MAIN_THREADS)
            acc2[i] = 0.f;
    }

    #pragma unroll 1
    for (int part = 0; part < NPART; ++part) {
        __syncthreads();   // prior sweep's rbuf reads + reds done
        {
            const float* base0 = (part == 0)
                ? rates_1st + (size_t)b0 * R1
                : rates_2nd + (size_t)b0 * R2 + (part - 1) * RPP;
            const float* base1 = (part == 0)
                ? rates_1st + (size_t)b1 * R1
                : rates_2nd + (size_t)b1 * R2 + (part - 1) * RPP;
            const float4* s0 = (const float4*)base0;
            const float4* s1 = (const float4*)base1;
            for (int i = tid; i < RPP / 4; i += MAIN_THREADS) {
                float4 r0 = __ldcs(s0 + i);
                float4 r1 = __ldcs(s1 + i);
                __half2 t[4];
                t[0] = __floats2half2_rn(r0.x, r1.x);
                t[1] = __floats2half2_rn(r0.y, r1.y);
                t[2] = __floats2half2_rn(r0.z, r1.z);
                t[3] = __floats2half2_rn(r0.w, r1.w);
                *(uint4*)(rbuf2h + 4 * i) = *(const uint4*)t;  // STS.128
            }
        }
        __syncthreads();

        if (part == 0)
            sweep2<false>(g_et[0] + tid, y2h, rbuf2h, acc_base);
        else if (part == 1)
            sweep2<true>(g_et[1] + tid, y2h, rbuf2h, acc_base);
        else
            sweep2<true>(g_et[2] + tid, y2h, rbuf2h, acc_base);
    }
    __syncthreads();

    // ---- write out both rows ----
    #pragma unroll
    for (int i = tid; i < S; i += MAIN_THREADS) {
        float2 t = *(const float2*)(acc2 + 2 * i);
        y_out[(size_t)b0 * S + i] = t.x;
        y_out[(size_t)b1 * S + i] = t.y;
    }
}

// ---------------- launch ----------------

extern "C" void kernel_launch(void* const* d_in, const int* in_sizes, int n_in,
                              void* d_out, int out_size) {
    const float* y_in      = (const float*)d_in[0];
    const float* rates_1st = (const float*)d_in[1];
    const float* rates_2nd = (const float*)d_in[2];
    const int*   inds_1r   = (const int*)d_in[3];
    const int*   inds_1p   = (const int*)d_in[4];
    const int*   inds_2r   = (const int*)d_in[5];
    const int*   inds_2p   = (const int*)d_in[6];
    float*       y_out     = (float*)d_out;

    cudaFuncSetAttribute(reaction_main_kernel,
                         cudaFuncAttributeMaxDynamicSharedMemorySize,
                         SMEM_BYTES);

    // Entry-stream build (rebuilt every launch; deterministic).
    hist_kernel<<<(R1 + R2 + 255) / 256, 256>>>(inds_1p, inds_2p);
    scan_kernel<<<NPART, 1024>>>();
    int scat_n = R1 + R2 + NPART * (PART_PAD - RPP);
    scatter_pad_kernel<<<(scat_n + 255) / 256, 256>>>(inds_1r, inds_1p, inds_2r, inds_2p);

    // Main pass: one CTA per TWO batch rows
    reaction_main_kernel<<<B / 2, MAIN_THREADS, SMEM_BYTES>>>(
        y_in, rates_1st, rates_2nd, y_out);
}

// round 12
// speedup vs baseline: 1.0793x; 1.0793x over previous
#include <cuda_runtime.h>
#include <cuda_fp16.h>
#include <stdint.h>

// Problem constants
#define B     1024
#define S     2048
#define R1    20000
#define R2    40000

#define MAIN_THREADS 512
#define NPART 3                    // part0 = rates_1st; part1,2 = rates_2nd halves
#define RPP   20000                // rates (and real entries) per partition
#define EPT   40                   // entries per thread per partition (pad 20480)
#define PART_PAD (EPT * MAIN_THREADS)   // 20480
#define KPAD  2048u                // pad-entry key (harmless acc slot)
#define SINK0 2049                 // 4 rotating sink slots: 2049..2052
#define ACC_SLOTS 2054
#define CHUNK 4                    // 4 buffers -> prefetch distance 3

// ---------------- static device scratch (no runtime allocation) ----------------
// g_counts starts zero (static zero-init); scan_kernel re-zeroes after reading.
__device__ int       g_counts[NPART][S];
__device__ int       g_cur[NPART][S];
// Key-grouped, transposed entry streams.
//   part0:  e = ra | k<<11 | rid<<23            (11 + 12 + 15 bits)
//   part1+: e = ra | rb<<11 | k<<22 | rid<<34   (11 + 11 + 12 + 15 bits)
__device__ uint64_t  g_et[NPART][PART_PAD];

__device__ __forceinline__ int transposeP(int pos) {
    return (pos % EPT) * MAIN_THREADS + pos / EPT;
}

// ---------------- prep kernels ----------------

__global__ void hist_kernel(const int* __restrict__ inds_1p,
                            const int* __restrict__ inds_2p) {
    int i = blockIdx.x * blockDim.x + threadIdx.x;
    if (i < R1) {
        atomicAdd(&g_counts[0][inds_1p[i]], 1);
    } else if (i < R1 + R2) {
        int j = i - R1;
        atomicAdd(&g_counts[1 + (j >= RPP)][inds_2p[j]], 1);
    }
}

// One CTA per partition: exclusive scan over its 2048 bins -> running cursors.
// Re-zeroes its counts slice (restores the zero-at-entry invariant).
__global__ void scan_kernel() {
    __shared__ int buf[2][S];
    const int tid  = threadIdx.x;       // 1024 threads, 2 elems each
    const int part = blockIdx.x;

    int* cnt = g_counts[part];
    int* cur = g_cur[part];

    buf[0][tid]        = cnt[tid];
    buf[0][tid + 1024] = cnt[tid + 1024];
    cnt[tid]        = 0;
    cnt[tid + 1024] = 0;
    __syncthreads();

    int src = 0;
    for (int off = 1; off < S; off <<= 1) {
        int i0 = tid, i1 = tid + 1024;
        int v0 = buf[src][i0] + (i0 >= off ? buf[src][i0 - off] : 0);
        int v1 = buf[src][i1] + (i1 >= off ? buf[src][i1 - off] : 0);
        __syncthreads();
        buf[1 - src][i0] = v0;
        buf[1 - src][i1] = v1;
        __syncthreads();
        src ^= 1;
    }
    cur[tid]        = (tid == 0) ? 0 : buf[src][tid - 1];
    cur[tid + 1024] = buf[src][tid + 1023];
}

// Scatter entries into key-grouped transposed slots + write pad entries.
__global__ void scatter_pad_kernel(const int* __restrict__ inds_1r,
                                   const int* __restrict__ inds_1p,
                                   const int* __restrict__ inds_2r,
                                   const int* __restrict__ inds_2p) {
    int i = blockIdx.x * blockDim.x + threadIdx.x;
    if (i < R1) {
        int p   = inds_1p[i];
        int pos = atomicAdd(&g_cur[0][p], 1);
        g_et[0][transposeP(pos)] =
              (uint64_t)(uint32_t)inds_1r[i]
            | ((uint64_t)(uint32_t)p << 11)
            | ((uint64_t)(uint32_t)i << 23);
    } else if (i < R1 + R2) {
        int j    = i - R1;
        int part = 1 + (j >= RPP);
        int rrel = j - (part - 1) * RPP;
        int p    = inds_2p[j];
        int pos  = atomicAdd(&g_cur[part][p], 1);
        g_et[part][transposeP(pos)] =
              (uint64_t)(uint32_t)inds_2r[2 * j]
            | ((uint64_t)(uint32_t)inds_2r[2 * j + 1] << 11)
            | ((uint64_t)(uint32_t)p                  << 22)
            | ((uint64_t)(uint32_t)rrel               << 34);
    } else if (i < R1 + R2 + NPART * (PART_PAD - RPP)) {
        int q    = i - (R1 + R2);
        int part = q / (PART_PAD - RPP);
        int slot = RPP + q % (PART_PAD - RPP);
        uint64_t e = (part == 0) ? ((uint64_t)KPAD << 11) : ((uint64_t)KPAD << 22);
        g_et[part][transposeP(slot)] = e;
    }
}

// ---------------- main kernel ----------------
// TWO batch rows per CTA; random-read tables (y, rates) packed __half2
// {row0,row1}; fp32 register run accumulation. Interior run closes are plain
// SMEM RMWs through a SEL-redirected address; the dummy (non-close) RMWs
// rotate over 4 sink slots so there is never a same-address LDS-after-STS
// stall. Entry chunks are quad-buffered (prefetch distance 3) so chunk-
// boundary LDG latency is fully covered. Slice-boundary runs (keys possibly
// shared with neighboring threads) are captured in registers and resolved
// with spread SMEM atomics after a barrier.
//
// SMEM: y2h(8KB) + acc2(16.4KB) + rbuf2h(80KB) = 104.6KB -> 2 CTAs/SM.

#define SMEM_BYTES (S * 4 + 2 * ACC_SLOTS * 4 + RPP * 4)

template <bool SECOND>
__device__ __forceinline__ void sweep2(
    const uint64_t* __restrict__ ep,      // g_et[part] + tid
    const __half2* __restrict__ y2h,
    const __half2* __restrict__ rbuf2h,
    float* __restrict__ acc2,
    unsigned& firstk, float& f0, float& f1, unsigned& fdone,
    unsigned& lastk, float& l0, float& l1)
{
    uint64_t buf[4][CHUNK];
    #pragma unroll
    for (int pc = 0; pc < 3; ++pc)
        #pragma unroll
        for (int u = 0; u < CHUNK; ++u)
            buf[pc][u] = ep[(pc * CHUNK + u) * MAIN_THREADS];

    unsigned curk = 0, rot = 0;
    float a0 = 0.f, a1 = 0.f;
    unsigned first_done = 0;
    firstk = SINK0; f0 = 0.f; f1 = 0.f;

    #pragma unroll
    for (int c = 0; c < EPT / CHUNK; ++c) {          // 10 chunks
        if (c + 3 < EPT / CHUNK) {                   // prefetch distance 3
            const uint64_t* np = ep + (c + 3) * CHUNK * MAIN_THREADS;
            #pragma unroll
            for (int u = 0; u < CHUNK; ++u)
                buf[(c + 3) & 3][u] = np[u * MAIN_THREADS];
        }
        #pragma unroll
        for (int u = 0; u < CHUNK; ++u) {
            uint64_t e = buf[c & 3][u];
            unsigned k;
            float v0, v1;
            if (SECOND) {
                unsigned ra  = (unsigned)e & 2047u;
                unsigned rb  = ((unsigned)(e >> 11)) & 2047u;
                k            = ((unsigned)(e >> 22)) & 4095u;
                unsigned rid = (unsigned)(e >> 34);
                float2 fa = __half22float2(y2h[ra]);     // 1 random LDS.32
                float2 fb = __half22float2(y2h[rb]);     // 1 random LDS.32
                float2 fr = __half22float2(rbuf2h[rid]); // 1 random LDS.32
                v0 = fa.x * fb.x * fr.x;
                v1 = fa.y * fb.y * fr.y;
            } else {
                unsigned ra  = (unsigned)e & 2047u;
                k            = ((unsigned)(e >> 11)) & 4095u;
                unsigned rid = (unsigned)(e >> 23);
                float2 fa = __half22float2(y2h[ra]);
                float2 fr = __half22float2(rbuf2h[rid]);
                v0 = fa.x * fr.x;
                v1 = fa.y * fr.y;
            }
            if (c == 0 && u == 0) {
                curk = k; a0 = v0; a1 = v1;      // prime first run
            } else {
                unsigned diff     = (k != curk) ? 1u : 0u;
                unsigned do_store = diff & first_done;
                // rotating sinks: dummy RMWs never hit the same address twice
                // within 4 entries -> no same-address LDS-after-STS stall.
                float* addr = do_store ? (acc2 + 2 * curk)
                                       : (acc2 + 2 * (SINK0 + rot));
                float2 t = *(float2*)addr;
                t.x += a0; t.y += a1;
                *(float2*)addr = t;
                rot = (rot + 1) & 3u;
                unsigned cap = diff & (1u - first_done);
                firstk = cap ? curk : firstk;
                f0     = cap ? a0   : f0;
                f1     = cap ? a1   : f1;
                first_done |= diff;
                a0 = diff ? v0 : (a0 + v0);
                a1 = diff ? v1 : (a1 + v1);
                curk = k;
            }
        }
    }
    fdone = first_done;
    lastk = curk; l0 = a0; l1 = a1;
}

__global__ __launch_bounds__(MAIN_THREADS, 2)
void reaction_main_kernel(const float* __restrict__ y_in,
                          const float* __restrict__ rates_1st,
                          const float* __restrict__ rates_2nd,
                          float* __restrict__ y_out) {
    extern __shared__ char smraw[];
    __half2* y2h    = (__half2*)smraw;                       // [S]
    float*   acc2   = (float*)(smraw + S * 4);               // [2*ACC_SLOTS]
    __half2* rbuf2h = (__half2*)(smraw + S * 4 + 2 * ACC_SLOTS * 4); // [RPP]

    const int b0  = 2 * blockIdx.x;
    const int b1  = b0 + 1;
    const int tid = threadIdx.x;

    // Load two y rows -> packed half2 (vector STS); zero the accumulator.
    {
        const float4* s0 = (const float4*)(y_in + (size_t)b0 * S);
        const float4* s1 = (const float4*)(y_in + (size_t)b1 * S);
        float4 r0 = s0[tid], r1 = s1[tid];
        __half2 t[4];
        t[0] = __floats2half2_rn(r0.x, r1.x);
        t[1] = __floats2half2_rn(r0.y, r1.y);
        t[2] = __floats2half2_rn(r0.z, r1.z);
        t[3] = __floats2half2_rn(r0.w, r1.w);
        *(uint4*)(y2h + 4 * tid) = *(const uint4*)t;         // STS.128
        #pragma unroll
        for (int i = tid; i < 2 * ACC_SLOTS; i += MAIN_THREADS)
            acc2[i] = 0.f;
    }

    #pragma unroll 1
    for (int part = 0; part < NPART; ++part) {
        __syncthreads();   // prior sweep's rbuf reads + stores done
        {
            const float* base0 = (part == 0)
                ? rates_1st + (size_t)b0 * R1
                : rates_2nd + (size_t)b0 * R2 + (part - 1) * RPP;
            const float* base1 = (part == 0)
                ? rates_1st + (size_t)b1 * R1
                : rates_2nd + (size_t)b1 * R2 + (part - 1) * RPP;
            const float4* s0 = (const float4*)base0;
            const float4* s1 = (const float4*)base1;
            for (int i = tid; i < RPP / 4; i += MAIN_THREADS) {
                float4 r0 = __ldcs(s0 + i);
                float4 r1 = __ldcs(s1 + i);
                __half2 t[4];
                t[0] = __floats2half2_rn(r0.x, r1.x);
                t[1] = __floats2half2_rn(r0.y, r1.y);
                t[2] = __floats2half2_rn(r0.z, r1.z);
                t[3] = __floats2half2_rn(r0.w, r1.w);
                *(uint4*)(rbuf2h + 4 * i) = *(const uint4*)t;  // STS.128
            }
        }
        __syncthreads();

        unsigned firstk, fdone, lastk;
        float f0, f1, l0, l1;
        if (part == 0)
            sweep2<false>(g_et[0] + tid, y2h, rbuf2h, acc2,
                          firstk, f0, f1, fdone, lastk, l0, l1);
        else if (part == 1)
            sweep2<true>(g_et[1] + tid, y2h, rbuf2h, acc2,
                         firstk, f0, f1, fdone, lastk, l0, l1);
        else
            sweep2<true>(g_et[2] + tid, y2h, rbuf2h, acc2,
                         firstk, f0, f1, fdone, lastk, l0, l1);

        __syncthreads();   // interior plain stores visible before boundary atomics
        atomicAdd(&acc2[2 * lastk],     l0);
        atomicAdd(&acc2[2 * lastk + 1], l1);
        if (fdone) {
            atomicAdd(&acc2[2 * firstk],     f0);
            atomicAdd(&acc2[2 * firstk + 1], f1);
        }
    }
    __syncthreads();

    // ---- write out both rows ----
    #pragma unroll
    for (int i = tid; i < S; i += MAIN_THREADS) {
        float2 t = *(const float2*)(acc2 + 2 * i);
        y_out[(size_t)b0 * S + i] = t.x;
        y_out[(size_t)b1 * S + i] = t.y;
    }
}

// ---------------- launch ----------------

extern "C" void kernel_launch(void* const* d_in, const int* in_sizes, int n_in,
                              void* d_out, int out_size) {
    const float* y_in      = (const float*)d_in[0];
    const float* rates_1st = (const float*)d_in[1];
    const float* rates_2nd = (const float*)d_in[2];
    const int*   inds_1r   = (const int*)d_in[3];
    const int*   inds_1p   = (const int*)d_in[4];
    const int*   inds_2r   = (const int*)d_in[5];
    const int*   inds_2p   = (const int*)d_in[6];
    float*       y_out     = (float*)d_out;

    cudaFuncSetAttribute(reaction_main_kernel,
                         cudaFuncAttributeMaxDynamicSharedMemorySize,
                         SMEM_BYTES);

    // Entry-stream build (rebuilt every launch; deterministic).
    hist_kernel<<<(R1 + R2 + 255) / 256, 256>>>(inds_1p, inds_2p);
    scan_kernel<<<NPART, 1024>>>();
    int scat_n = R1 + R2 + NPART * (PART_PAD - RPP);
    scatter_pad_kernel<<<(scat_n + 255) / 256, 256>>>(inds_1r, inds_1p, inds_2r, inds_2p);

    // Main pass: one CTA per TWO batch rows
    reaction_main_kernel<<<B / 2, MAIN_THREADS, SMEM_BYTES>>>(
        y_in, rates_1st, rates_2nd, y_out);
}